// round 7
// baseline (speedup 1.0000x reference)
#include <cuda_runtime.h>
#include <cuda_bf16.h>

// Problem constants (reference: B=32, A=4096, P=8388608, E=8)
#define Bn 32
#define An 4096
#define En 8

#define NBLK 32
#define PT 256
#define WPB (PT / 32)             // 8 warps/block
#define NW (NBLK * WPB)           // 256 warps
#define PREFIX (NW * 32)          // 8192 pairs scanned in stage A (1/lane)
#define WTILE 128                 // fallback tile (32 lanes x int4)

// Persistent device state. Zero at module load; last block resets after each
// run so every graph replay starts clean.
__device__ unsigned g_done;   // bit b => out[b]=1 (too_close OR eng_big)
__device__ unsigned g_ready;  // stage-A rendezvous counter (one add per warp)
__device__ unsigned g_count;  // completion ticket

// Non-hoistable L2 poll.
__device__ __forceinline__ unsigned poll_u32(const unsigned* p) {
    unsigned v;
    asm volatile("ld.global.cg.u32 %0, [%1];" : "=r"(v) : "l"(p) : "memory");
    return v;
}

__global__ void __launch_bounds__(PT)
k_fused(const float* __restrict__ pos,
        const float* __restrict__ eng,
        const int* __restrict__ elm,
        const float* __restrict__ radius,
        const float* __restrict__ eng_atm,
        const int* __restrict__ nn,
        const int* __restrict__ ii,
        const int* __restrict__ jj,
        int P,
        float* __restrict__ out, int out_size) {
    __shared__ float s_rad[En];
    __shared__ unsigned s_ticket;

    const int tid  = threadIdx.x;
    const int bid  = blockIdx.x;
    const int wid  = tid >> 5;
    const int lane = tid & 31;
    const int gw   = bid * WPB + wid;      // global warp id

    if (tid < En) s_rad[tid] = radius[tid];
    __syncthreads();

    // ---- Stage A: one pair per lane from the global prefix. Single latency
    // chain: idx loads -> gathers -> REDUX -> RED.
    {
        int q = gw * 32 + lane;
        unsigned local = 0u;
        if (q < P) {
            int nb = __ldg(nn + q);
            int ai = nb * An + __ldg(ii + q);
            int aj = nb * An + __ldg(jj + q);
            float ax = __ldg(pos + 3 * ai + 0);
            float ay = __ldg(pos + 3 * ai + 1);
            float az = __ldg(pos + 3 * ai + 2);
            float bx = __ldg(pos + 3 * aj + 0);
            float by = __ldg(pos + 3 * aj + 1);
            float bz = __ldg(pos + 3 * aj + 2);
            float rs = s_rad[__ldg(elm + ai)] + s_rad[__ldg(elm + aj)];
            float dx = bx - ax, dy = by - ay, dz = bz - az;
            float sod = dx * dx + dy * dy + dz * dz;
            if (rs * rs >= sod) local = 1u << nb;
        }
        unsigned wbits = __reduce_or_sync(0xFFFFFFFFu, local);
        __threadfence();                   // order RED before the ready-add
        if (lane == 0) {
            if (wbits) atomicOr(&g_done, wbits);   // RED, fire-and-forget
            atomicAdd(&g_ready, 1u);               // announce stage A done
        }
    }

    // ---- Deterministic rendezvous: all warps resident (single wave), every
    // warp increments g_ready exactly once -> guaranteed termination in
    // ~max(stage A latency). No sleeps.
    while (poll_u32(&g_ready) < NW) { }
    __threadfence();                       // acquire: REDs visible after adds
    unsigned m = poll_u32(&g_done);        // all stage-A bits now included

    if (m != 0xFFFFFFFFu) {
        // ---- Fallback 1 (normally skipped): scan remaining pairs [PREFIX,P).
        const long long ntiles =
            ((long long)P - PREFIX + WTILE - 1) / WTILE;
        for (long long t = gw; t < ntiles; t += NW) {
            m = poll_u32(&g_done);
            if (m == 0xFFFFFFFFu) break;

            long long idx = (long long)PREFIX + t * WTILE + lane * 4;
            unsigned local = 0u;
            if (idx + 4 <= (long long)P) {
                int4 n4 = __ldg((const int4*)(nn + idx));
                int4 i4 = __ldg((const int4*)(ii + idx));
                int4 j4 = __ldg((const int4*)(jj + idx));
                int na[4] = {n4.x, n4.y, n4.z, n4.w};
                int ia[4] = {i4.x, i4.y, i4.z, i4.w};
                int ja[4] = {j4.x, j4.y, j4.z, j4.w};
                #pragma unroll
                for (int k = 0; k < 4; ++k) {
                    int nb = na[k];
                    if ((m >> nb) & 1u) continue;
                    int ai = nb * An + ia[k];
                    int aj = nb * An + ja[k];
                    float dx = __ldg(pos + 3 * aj + 0) - __ldg(pos + 3 * ai + 0);
                    float dy = __ldg(pos + 3 * aj + 1) - __ldg(pos + 3 * ai + 1);
                    float dz = __ldg(pos + 3 * aj + 2) - __ldg(pos + 3 * ai + 2);
                    float sod = dx * dx + dy * dy + dz * dz;
                    float rs = s_rad[__ldg(elm + ai)] + s_rad[__ldg(elm + aj)];
                    if (rs * rs >= sod) local |= 1u << nb;
                }
            } else if (idx < (long long)P) {
                for (int k = 0; k < 4; ++k) {
                    long long q = idx + k;
                    if (q >= (long long)P) break;
                    int nb = __ldg(nn + q);
                    if ((m >> nb) & 1u) continue;
                    int ai = nb * An + __ldg(ii + q);
                    int aj = nb * An + __ldg(jj + q);
                    float dx = __ldg(pos + 3 * aj + 0) - __ldg(pos + 3 * ai + 0);
                    float dy = __ldg(pos + 3 * aj + 1) - __ldg(pos + 3 * ai + 1);
                    float dz = __ldg(pos + 3 * aj + 2) - __ldg(pos + 3 * ai + 2);
                    float sod = dx * dx + dy * dy + dz * dz;
                    float rs = s_rad[__ldg(elm + ai)] + s_rad[__ldg(elm + aj)];
                    if (rs * rs >= sod) local |= 1u << nb;
                }
            }
            unsigned wbits = __reduce_or_sync(0xFFFFFFFFu, local) & ~m;
            if (wbits && lane == 0) atomicOr(&g_done, wbits);
            m |= wbits;
            if (m == 0xFFFFFFFFu) break;
        }

        // ---- Fallback 2: eng_big reduction for still-unflagged structures.
        // Warp 0 of block b handles structure b (NBLK == Bn == 32).
        if (bid < Bn && wid == 0) {
            unsigned cur = poll_u32(&g_done);
            if (!((cur >> bid) & 1u)) {
                float av = __ldg(eng_atm + (lane & (En - 1)));
                const int4* row = (const int4*)(elm + bid * An);
                float s = 0.f;
                #pragma unroll 4
                for (int t2 = lane; t2 < An / 4; t2 += 32) {
                    int4 e4 = __ldg(row + t2);
                    s += __shfl_sync(0xFFFFFFFFu, av, e4.x & 7);
                    s += __shfl_sync(0xFFFFFFFFu, av, e4.y & 7);
                    s += __shfl_sync(0xFFFFFFFFu, av, e4.z & 7);
                    s += __shfl_sync(0xFFFFFFFFu, av, e4.w & 7);
                }
                #pragma unroll
                for (int o = 16; o > 0; o >>= 1)
                    s += __shfl_down_sync(0xFFFFFFFFu, s, o);
                s = __shfl_sync(0xFFFFFFFFu, s, 0);
                if (lane == 0 && __ldg(eng + bid) >= s)
                    atomicOr(&g_done, 1u << bid);
            }
        }
    }

    // ---- Completion: last block writes output, resets persistent state.
    // (Reset must wait for all readers of g_done/g_ready -> ticket.)
    __threadfence();
    __syncthreads();
    if (tid == 0) s_ticket = atomicAdd(&g_count, 1u);
    __syncthreads();

    if (s_ticket == (unsigned)(gridDim.x - 1)) {
        __threadfence();
        unsigned fm = atomicOr(&g_done, 0u);   // coherent final mask
        for (int b = tid; b < out_size; b += PT)
            out[b] = (b < Bn) ? (float)((fm >> b) & 1u) : 0.0f;
        __syncthreads();
        if (tid == 0) { g_done = 0u; g_ready = 0u; g_count = 0u; }
    }
}

// ---------------------------------------------------------------------------
// Inputs (metadata order): pos[B,A,3] f32, eng[B] f32, elm[B,A] i32,
// radius[E] f32, eng_atm[E] f32, n[P] i32, i[P] i32, j[P] i32.
// Output: float32[B] (0.0 / 1.0).
extern "C" void kernel_launch(void* const* d_in, const int* in_sizes, int n_in,
                              void* d_out, int out_size) {
    const float* pos     = (const float*)d_in[0];
    const float* eng     = (const float*)d_in[1];
    const int*   elm     = (const int*)d_in[2];
    const float* radius  = (const float*)d_in[3];
    const float* eng_atm = (const float*)d_in[4];
    const int*   nn      = (const int*)d_in[5];
    const int*   ii      = (const int*)d_in[6];
    const int*   jj      = (const int*)d_in[7];
    int P = in_sizes[5];

    k_fused<<<NBLK, PT>>>(pos, eng, elm, radius, eng_atm, nn, ii, jj, P,
                          (float*)d_out, out_size);
}